// round 15
// baseline (speedup 1.0000x reference)
#include <cuda_runtime.h>
#include <cuda_fp16.h>
#include <mma.h>
#include <math.h>

using namespace nvcuda;

#define NN 20000
#define NPAD 20096   // 157 * 128, so wmma tile rows never overrun
#define EE 320000
#define ETOT (EE + NN)

// ---------------- device scratch (no allocations allowed) ----------------
__device__ __align__(16) float g_hA[NN * 64];
__device__ __align__(16) float g_hB[NN * 64];
// hproj row layout (256 halves): offset = pair*8 + head*2 + (ch&1), pair = (ch within head)/2.
// Lane L's uint4 at offset 16B*L holds its channel pair (2L,2L+1) for all 4 heads.
__device__ __align__(16) __half g_hproj[NPAD * 256];
__device__ __align__(16) float g_asrc[NN * 4];
__device__ __align__(16) float g_adst[NN * 4];
__device__ __align__(16) float g_alpha[ETOT * 4];   // per-edge unnormalized softmax weights
__device__ __align__(16) float g_wad[3][512];       // [layer][k*8 + j], j<4: Wa, j>=4: Wd
__device__ __align__(16) int g_deg[NN];
__device__ __align__(16) int g_rowptr[NN + 4];
__device__ __align__(16) int g_cursor[NN];
__device__ int g_esrc[ETOT];
__device__ int g_is64;

// ---------------- edge dtype detection (int64 vs int32) ----------------
__global__ void detect_kernel(const void* edges) {
    const long long* p = (const long long*)edges;
    int lane = threadIdx.x;
    bool ok = true;
    for (int i = lane; i < 512; i += 32) {
        long long v = p[i];
        if (v < 0 || v >= NN) ok = false;
    }
    unsigned m = __ballot_sync(0xffffffffu, ok);
    if (lane == 0) g_is64 = (m == 0xffffffffu) ? 1 : 0;
}

// ---------------- encoder MLP (x[N,8]->32->64, ELU) + deg init (fused) ----------------
__global__ void encode_kernel(const float* __restrict__ x,
                              const float* __restrict__ W1, const float* __restrict__ b1,
                              const float* __restrict__ W2, const float* __restrict__ b2) {
    __shared__ float sW1[8 * 32], sb1[32], sW2[32 * 64], sb2[64];
    for (int i = threadIdx.x; i < 256; i += blockDim.x) sW1[i] = W1[i];
    for (int i = threadIdx.x; i < 32; i += blockDim.x) sb1[i] = b1[i];
    for (int i = threadIdx.x; i < 2048; i += blockDim.x) sW2[i] = W2[i];
    for (int i = threadIdx.x; i < 64; i += blockDim.x) sb2[i] = b2[i];
    __syncthreads();
    int v = blockIdx.x * blockDim.x + threadIdx.x;
    if (v >= NN) return;
    g_deg[v] = 1;  // self-loop (fused initdeg)
    float xr[8];
#pragma unroll
    for (int k = 0; k < 8; k++) xr[k] = x[v * 8 + k];
    float t[32];
#pragma unroll
    for (int j = 0; j < 32; j++) {
        float s = sb1[j];
#pragma unroll
        for (int k = 0; k < 8; k++) s = fmaf(xr[k], sW1[k * 32 + j], s);
        t[j] = (s > 0.f) ? s : expm1f(s);
    }
    for (int j = 0; j < 64; j++) {
        float s = sb2[j];
#pragma unroll
        for (int k = 0; k < 32; k++) s = fmaf(t[k], sW2[k * 64 + j], s);
        g_hA[v * 64 + j] = (s > 0.f) ? s : expm1f(s);
    }
}

// ---------------- CSR build ----------------
__global__ void hist_kernel(const void* edges) {
    int base = (blockIdx.x * blockDim.x + threadIdx.x) * 4;
    if (base >= EE) return;
    if (g_is64) {
        const long long* p = (const long long*)edges + EE + base;
        longlong4 v = *(const longlong4*)p;
        atomicAdd(&g_deg[(int)v.x], 1);
        atomicAdd(&g_deg[(int)v.y], 1);
        atomicAdd(&g_deg[(int)v.z], 1);
        atomicAdd(&g_deg[(int)v.w], 1);
    } else {
        const int* p = (const int*)edges + EE + base;
        int4 v = *(const int4*)p;
        atomicAdd(&g_deg[v.x], 1);
        atomicAdd(&g_deg[v.y], 1);
        atomicAdd(&g_deg[v.z], 1);
        atomicAdd(&g_deg[v.w], 1);
    }
}

// vectorized: 5x int4 loads, 10x int4 stores per thread
__global__ void scan_kernel() {
    __shared__ int sums[1024];
    int t = threadIdx.x;
    int base = t * 20;
    int local[20];
    int s = 0;
    if (base < NN) {  // NN = 1000*20, so t<1000 fully in range
        const int4* dp = reinterpret_cast<const int4*>(&g_deg[base]);
#pragma unroll
        for (int q = 0; q < 5; q++) {
            int4 v = dp[q];
            local[q * 4 + 0] = s; s += v.x;
            local[q * 4 + 1] = s; s += v.y;
            local[q * 4 + 2] = s; s += v.z;
            local[q * 4 + 3] = s; s += v.w;
        }
    } else {
#pragma unroll
        for (int i = 0; i < 20; i++) local[i] = 0;
    }
    sums[t] = s;
    __syncthreads();
    for (int off = 1; off < 1024; off <<= 1) {
        int v = (t >= off) ? sums[t - off] : 0;
        __syncthreads();
        sums[t] += v;
        __syncthreads();
    }
    int prefix = (t > 0) ? sums[t - 1] : 0;
    if (base < NN) {
        int4* rp = reinterpret_cast<int4*>(&g_rowptr[base]);
        int4* cp = reinterpret_cast<int4*>(&g_cursor[base]);
#pragma unroll
        for (int q = 0; q < 5; q++) {
            int4 v = make_int4(prefix + local[q * 4], prefix + local[q * 4 + 1],
                               prefix + local[q * 4 + 2], prefix + local[q * 4 + 3]);
            rp[q] = v;
            cp[q] = v;
        }
    }
    if (t == 1023) g_rowptr[NN] = sums[1023];
}

__global__ void scatter_kernel(const void* edges) {
    int e = blockIdx.x * blockDim.x + threadIdx.x;
    if (e < EE) {
        int s, d;
        if (g_is64) {
            s = (int)((const long long*)edges)[e];
            d = (int)((const long long*)edges)[EE + e];
        } else {
            s = ((const int*)edges)[e];
            d = ((const int*)edges)[EE + e];
        }
        int pos = atomicAdd(&g_cursor[d], 1);
        g_esrc[pos] = s;
    } else if (e < EE + NN) {
        int v = e - EE;
        int pos = atomicAdd(&g_cursor[v], 1);
        g_esrc[pos] = v;
    }
}

// ---------------- Wad prep: Wad[k][j] = sum_c W[k, h*64+c] * att[h][c] ----------------
__global__ void wadprep_kernel(const float* __restrict__ W,
                               const float* __restrict__ as_, const float* __restrict__ ad_,
                               int l) {
    for (int o = threadIdx.x; o < 512; o += blockDim.x) {
        int k = o >> 3, j = o & 7;
        const float* vec = (j < 4) ? as_ : ad_;
        int h = j & 3;
        const float* wr = W + k * 256 + h * 64;
        const float* vr = vec + h * 64;
        float s = 0.f;
#pragma unroll
        for (int c = 0; c < 64; c++) s = fmaf(wr[c], vr[c], s);
        g_wad[l][k * 8 + j] = s;
    }
}

// ---------------- attention scores from x: a_src/a_dst = x @ Wad (fp32) ----------------
__global__ void att_kernel(int l, int srcA) {
    const float* xin = srcA ? g_hA : g_hB;
    __shared__ float sW[512];
    for (int i = threadIdx.x; i < 512; i += blockDim.x) sW[i] = g_wad[l][i];
    __syncthreads();
    int v = blockIdx.x * blockDim.x + threadIdx.x;
    if (v >= NN) return;
    float acc[8] = {0.f, 0.f, 0.f, 0.f, 0.f, 0.f, 0.f, 0.f};
    const float4* xr = reinterpret_cast<const float4*>(xin + v * 64);
#pragma unroll
    for (int q = 0; q < 16; q++) {
        float4 xv = xr[q];
        const float* w0 = &sW[(q * 4 + 0) * 8];
        const float* w1 = &sW[(q * 4 + 1) * 8];
        const float* w2 = &sW[(q * 4 + 2) * 8];
        const float* w3 = &sW[(q * 4 + 3) * 8];
#pragma unroll
        for (int j = 0; j < 8; j++) {
            acc[j] = fmaf(xv.x, w0[j], acc[j]);
            acc[j] = fmaf(xv.y, w1[j], acc[j]);
            acc[j] = fmaf(xv.z, w2[j], acc[j]);
            acc[j] = fmaf(xv.w, w3[j], acc[j]);
        }
    }
#pragma unroll
    for (int j = 0; j < 4; j++) {
        g_asrc[v * 4 + j] = acc[j];
        g_adst[v * 4 + j] = acc[j + 4];
    }
}

// ---- tensor-core projection GEMM: WMMA fp32 acc, fp16 head-interleaved output ----
#define A_STRIDE 72    // halves per A smem row (64 + 8 pad)
#define B_STRIDE 136   // halves per B smem row (128 + 8 pad)
#define STAGE_OFF (128 * A_STRIDE * 2 + 64 * B_STRIDE * 2)      // 35840
#define GEMM_SMEM_BYTES (STAGE_OFF + 8 * 256 * 4)                // 44032

__global__ void __launch_bounds__(256) gemm_kernel(const float* __restrict__ B, int srcA) {
    const float* A = srcA ? g_hA : g_hB;
    __shared__ __align__(16) char smem_raw[GEMM_SMEM_BYTES];
    __half* Ah = reinterpret_cast<__half*>(smem_raw);
    __half* Bh = reinterpret_cast<__half*>(smem_raw + 128 * A_STRIDE * 2);
    int tid = threadIdx.x;
    int lane = tid & 31, w = tid >> 5;
    float* st = reinterpret_cast<float*>(smem_raw + STAGE_OFF) + w * 256;
    int rowBase = blockIdx.x * 128;
    int colBase = blockIdx.y * 128;

    // load A tile [128 x 64] fp32 -> fp16
    {
        int r = tid >> 1, cpart = (tid & 1) * 32;
        int gr = rowBase + r;
        if (gr < NN) {
            const float4* src = reinterpret_cast<const float4*>(&A[gr * 64 + cpart]);
#pragma unroll
            for (int j = 0; j < 8; j++) {
                float4 v = src[j];
                *reinterpret_cast<__half2*>(&Ah[r * A_STRIDE + cpart + j * 4]) = __floats2half2_rn(v.x, v.y);
                *reinterpret_cast<__half2*>(&Ah[r * A_STRIDE + cpart + j * 4 + 2]) = __floats2half2_rn(v.z, v.w);
            }
        } else {
            __half2 z = __floats2half2_rn(0.f, 0.f);
#pragma unroll
            for (int j = 0; j < 8; j++) {
                *reinterpret_cast<__half2*>(&Ah[r * A_STRIDE + cpart + j * 4]) = z;
                *reinterpret_cast<__half2*>(&Ah[r * A_STRIDE + cpart + j * 4 + 2]) = z;
            }
        }
    }
    // load B tile [64 x 128] fp32 -> fp16
    {
        int k = tid >> 2, cpart = (tid & 3) * 32;
        const float4* src = reinterpret_cast<const float4*>(&B[k * 256 + colBase + cpart]);
#pragma unroll
        for (int j = 0; j < 8; j++) {
            float4 v = src[j];
            *reinterpret_cast<__half2*>(&Bh[k * B_STRIDE + cpart + j * 4]) = __floats2half2_rn(v.x, v.y);
            *reinterpret_cast<__half2*>(&Bh[k * B_STRIDE + cpart + j * 4 + 2]) = __floats2half2_rn(v.z, v.w);
        }
    }
    __syncthreads();

    wmma::fragment<wmma::accumulator, 16, 16, 16, float> acc[8];
#pragma unroll
    for (int n = 0; n < 8; n++) wmma::fill_fragment(acc[n], 0.f);
#pragma unroll
    for (int k = 0; k < 4; k++) {
        wmma::fragment<wmma::matrix_a, 16, 16, 16, __half, wmma::row_major> af;
        wmma::load_matrix_sync(af, Ah + (w * 16) * A_STRIDE + k * 16, A_STRIDE);
#pragma unroll
        for (int n = 0; n < 8; n++) {
            wmma::fragment<wmma::matrix_b, 16, 16, 16, __half, wmma::row_major> bf;
            wmma::load_matrix_sync(bf, Bh + (k * 16) * B_STRIDE + n * 16, B_STRIDE);
            wmma::mma_sync(acc[n], af, bf, acc[n]);
        }
    }

    // epilogue: per-warp staging, fp32 -> fp16, head-interleaved half2 stores
    int rr = lane >> 1, cc = (lane & 1) * 8;
#pragma unroll
    for (int n = 0; n < 8; n++) {
        wmma::store_matrix_sync(st, acc[n], 16, wmma::mem_row_major);
        __syncwarp();
        float4 v0 = *reinterpret_cast<const float4*>(st + rr * 16 + cc);
        float4 v1 = *reinterpret_cast<const float4*>(st + rr * 16 + cc + 4);
        int gcol0 = colBase + n * 16 + cc;   // even; 8-col run stays within one head
        int head = gcol0 >> 6;
        int pair0 = (gcol0 & 63) >> 1;
        __half* dst = &g_hproj[(size_t)(rowBase + w * 16 + rr) * 256 + head * 2];
        *reinterpret_cast<__half2*>(dst + (pair0 + 0) * 8) = __floats2half2_rn(v0.x, v0.y);
        *reinterpret_cast<__half2*>(dst + (pair0 + 1) * 8) = __floats2half2_rn(v0.z, v0.w);
        *reinterpret_cast<__half2*>(dst + (pair0 + 2) * 8) = __floats2half2_rn(v1.x, v1.y);
        *reinterpret_cast<__half2*>(dst + (pair0 + 3) * 8) = __floats2half2_rn(v1.z, v1.w);
        __syncwarp();
    }
}

// ---------------- GAT edge pass: alpha cache + single-LDG.128 interleaved gather ----------------
__device__ __forceinline__ float lrelu(float x) { return fmaxf(x, 0.2f * x); }

__global__ void __launch_bounds__(256) gat_edge_kernel(const float* __restrict__ bias, int srcA) {
    const float* xin = srcA ? g_hA : g_hB;
    float* xout = srcA ? g_hB : g_hA;
    int warp = (blockIdx.x * blockDim.x + threadIdx.x) >> 5;
    int lane = threadIdx.x & 31;
    if (warp >= NN) return;
    int beg = g_rowptr[warp], end = g_rowptr[warp + 1];
    float4 adv = *reinterpret_cast<const float4*>(&g_adst[warp * 4]);

    // pass 1: unnormalized weights w = exp(lrelu(a_src+a_dst)); store + sum.
    float s0 = 0.f, s1 = 0.f, s2 = 0.f, s3 = 0.f;
    for (int e = beg + lane; e < end; e += 32) {
        int s = g_esrc[e];
        float4 av = *reinterpret_cast<const float4*>(&g_asrc[s * 4]);
        float4 wv;
        wv.x = __expf(lrelu(av.x + adv.x));
        wv.y = __expf(lrelu(av.y + adv.y));
        wv.z = __expf(lrelu(av.z + adv.z));
        wv.w = __expf(lrelu(av.w + adv.w));
        *reinterpret_cast<float4*>(&g_alpha[(size_t)e * 4]) = wv;
        s0 += wv.x; s1 += wv.y; s2 += wv.z; s3 += wv.w;
    }
#pragma unroll
    for (int o = 16; o > 0; o >>= 1) {
        s0 += __shfl_xor_sync(0xffffffffu, s0, o);
        s1 += __shfl_xor_sync(0xffffffffu, s1, o);
        s2 += __shfl_xor_sync(0xffffffffu, s2, o);
        s3 += __shfl_xor_sync(0xffffffffu, s3, o);
    }
    float i0 = 1.f / (s0 + 1e-16f);
    float i1 = 1.f / (s1 + 1e-16f);
    float i2 = 1.f / (s2 + 1e-16f);
    float i3 = 1.f / (s3 + 1e-16f);

    // pass 2: one uint4 per edge per lane = lane's channel pair for all 4 heads.
    float accx_a = 0.f, accy_a = 0.f, accx_b = 0.f, accy_b = 0.f;
    for (int base = beg; base < end; base += 32) {
        int cnt = min(32, end - base);
        int s = 0;
        float w0 = 0.f, w1 = 0.f, w2 = 0.f, w3 = 0.f;
        if (lane < cnt) {
            s = g_esrc[base + lane];
            float4 wv = *reinterpret_cast<const float4*>(&g_alpha[(size_t)(base + lane) * 4]);
            w0 = wv.x * i0;
            w1 = wv.y * i1;
            w2 = wv.z * i2;
            w3 = wv.w * i3;
        }
        for (int j = 0; j < cnt; j++) {
            int sj = __shfl_sync(0xffffffffu, s, j);
            float w0j = __shfl_sync(0xffffffffu, w0, j);
            float w1j = __shfl_sync(0xffffffffu, w1, j);
            float w2j = __shfl_sync(0xffffffffu, w2, j);
            float w3j = __shfl_sync(0xffffffffu, w3, j);
            uint4 v = __ldg(reinterpret_cast<const uint4*>(g_hproj + (size_t)sj * 256) + lane);
            const __half2* h2 = reinterpret_cast<const __half2*>(&v);
            float2 f0 = __half22float2(h2[0]);   // head 0, chans 2l,2l+1
            float2 f1 = __half22float2(h2[1]);   // head 1
            float2 f2 = __half22float2(h2[2]);   // head 2
            float2 f3 = __half22float2(h2[3]);   // head 3
            accx_a = fmaf(w0j, f0.x, accx_a);
            accy_a = fmaf(w0j, f0.y, accy_a);
            accx_b = fmaf(w1j, f1.x, accx_b);
            accy_b = fmaf(w1j, f1.y, accy_b);
            accx_a = fmaf(w2j, f2.x, accx_a);
            accy_a = fmaf(w2j, f2.y, accy_a);
            accx_b = fmaf(w3j, f3.x, accx_b);
            accy_b = fmaf(w3j, f3.y, accy_b);
        }
    }
    int c0 = lane * 2;
    float2 bv = *reinterpret_cast<const float2*>(&bias[c0]);
    float2 xv = *reinterpret_cast<const float2*>(&xin[warp * 64 + c0]);
    float2 ov;
    ov.x = (accx_a + accx_b) * 0.25f + bv.x + xv.x;
    ov.y = (accy_a + accy_b) * 0.25f + bv.y + xv.y;
    *reinterpret_cast<float2*>(&xout[warp * 64 + c0]) = ov;
}

// ---------------- output MLP: h3[N,64] -> 64 -> 32 -> 8 ----------------
__global__ void __launch_bounds__(64) outmlp_kernel(
    const float* __restrict__ W1, const float* __restrict__ b1,
    const float* __restrict__ W2, const float* __restrict__ b2,
    const float* __restrict__ W3, const float* __restrict__ b3,
    float* __restrict__ out) {
    __shared__ float sW1[64 * 64], sb1[64], sW2[64 * 32], sb2[32], sW3[32 * 8], sb3[8];
    __shared__ float sh[64 * 65];
    int tid = threadIdx.x;
    for (int i = tid; i < 4096; i += 64) sW1[i] = W1[i];
    if (tid < 64) sb1[tid] = b1[tid];
    for (int i = tid; i < 2048; i += 64) sW2[i] = W2[i];
    if (tid < 32) sb2[tid] = b2[tid];
    for (int i = tid; i < 256; i += 64) sW3[i] = W3[i];
    if (tid < 8) sb3[tid] = b3[tid];
    int vbase = blockIdx.x * 64;
    for (int i = tid; i < 64 * 64; i += 64) {
        int r = i >> 6, c = i & 63;
        int v = vbase + r;
        sh[r * 65 + c] = (v < NN) ? g_hB[v * 64 + c] : 0.f;
    }
    __syncthreads();
    int v = vbase + tid;
    if (v >= NN) return;
    const float* hr = &sh[tid * 65];
    float t1[64];
    for (int j = 0; j < 64; j++) {
        float s = sb1[j];
#pragma unroll
        for (int k = 0; k < 64; k++) s = fmaf(hr[k], sW1[k * 64 + j], s);
        t1[j] = (s > 0.f) ? s : expm1f(s);
    }
    float t2[32];
    for (int j = 0; j < 32; j++) {
        float s = sb2[j];
#pragma unroll
        for (int k = 0; k < 64; k++) s = fmaf(t1[k], sW2[k * 32 + j], s);
        t2[j] = (s > 0.f) ? s : expm1f(s);
    }
    for (int j = 0; j < 8; j++) {
        float s = sb3[j];
#pragma unroll
        for (int k = 0; k < 32; k++) s = fmaf(t2[k], sW3[k * 8 + j], s);
        out[v * 8 + j] = s;
    }
}

// ---------------- launch ----------------
extern "C" void kernel_launch(void* const* d_in, const int* in_sizes, int n_in,
                              void* d_out, int out_size) {
    const float* x = (const float*)d_in[0];
    const void* edges = d_in[1];
    const float* Wenc1 = (const float*)d_in[2];
    const float* benc1 = (const float*)d_in[3];
    const float* Wenc2 = (const float*)d_in[4];
    const float* benc2 = (const float*)d_in[5];
    const float* Wg[3] = {(const float*)d_in[6], (const float*)d_in[10], (const float*)d_in[14]};
    const float* as_[3] = {(const float*)d_in[7], (const float*)d_in[11], (const float*)d_in[15]};
    const float* ad_[3] = {(const float*)d_in[8], (const float*)d_in[12], (const float*)d_in[16]};
    const float* bg[3] = {(const float*)d_in[9], (const float*)d_in[13], (const float*)d_in[17]};
    const float* Wo1 = (const float*)d_in[18];
    const float* bo1 = (const float*)d_in[19];
    const float* Wo2 = (const float*)d_in[20];
    const float* bo2 = (const float*)d_in[21];
    const float* Wo3 = (const float*)d_in[22];
    const float* bo3 = (const float*)d_in[23];
    float* out = (float*)d_out;

    // gemm (layer 1) at launch index 3 for ncu visibility
    detect_kernel<<<1, 32>>>(edges);                                          // 0
    encode_kernel<<<(NN + 255) / 256, 256>>>(x, Wenc1, benc1, Wenc2, benc2);  // 1
    hist_kernel<<<(EE / 4 + 255) / 256, 256>>>(edges);                        // 2
    gemm_kernel<<<dim3(157, 2), 256>>>(Wg[0], 1);                             // 3
    scan_kernel<<<1, 1024>>>();                                               // 4
    scatter_kernel<<<(EE + NN + 255) / 256, 256>>>(edges);                    // 5
    wadprep_kernel<<<1, 256>>>(Wg[0], as_[0], ad_[0], 0);                     // 6
    att_kernel<<<(NN + 255) / 256, 256>>>(0, 1);                              // 7
    gat_edge_kernel<<<2500, 256>>>(bg[0], 1);                                 // 8

    int srcA = 0;
    for (int l = 1; l < 3; l++) {
        wadprep_kernel<<<1, 256>>>(Wg[l], as_[l], ad_[l], l);
        gemm_kernel<<<dim3(157, 2), 256>>>(Wg[l], srcA);
        att_kernel<<<(NN + 255) / 256, 256>>>(l, srcA);
        gat_edge_kernel<<<2500, 256>>>(bg[l], srcA);
        srcA ^= 1;
    }
    // after 3 layers result is in g_hB (A->B->A->B)
    outmlp_kernel<<<(NN + 63) / 64, 64>>>(Wo1, bo1, Wo2, bo2, Wo3, bo3, out);
}

// round 17
// speedup vs baseline: 1.0594x; 1.0594x over previous
#include <cuda_runtime.h>
#include <cuda_fp16.h>
#include <mma.h>
#include <math.h>

using namespace nvcuda;

#define NN 20000
#define NPAD 20096   // 157 * 128, so wmma tile rows never overrun
#define EE 320000
#define ETOT (EE + NN)

// ---------------- device scratch (no allocations allowed) ----------------
__device__ __align__(16) float g_hA[NN * 64];
__device__ __align__(16) float g_hB[NN * 64];
// hproj row layout (256 halves): offset = pair*8 + head*2 + (ch&1), pair = (ch within head)/2.
// Lane L's uint4 at offset 16B*L holds its channel pair (2L,2L+1) for all 4 heads.
__device__ __align__(16) __half g_hproj[NPAD * 256];
__device__ __align__(16) float g_asrc[NN * 4];
__device__ __align__(16) float g_adst[NN * 4];
__device__ __align__(16) float g_alpha[ETOT * 4];   // per-edge unnormalized softmax weights
__device__ __align__(16) float g_wad[3][512];       // [layer][k*8 + j], j<4: Wa, j>=4: Wd
__device__ __align__(16) int g_deg[NN];
__device__ __align__(16) int g_rowptr[NN + 4];
__device__ __align__(16) int g_cursor[NN];
__device__ int g_esrc[ETOT];
__device__ int g_is64;

// ---------------- edge dtype detection (int64 vs int32) ----------------
__global__ void detect_kernel(const void* edges) {
    const long long* p = (const long long*)edges;
    int lane = threadIdx.x;
    bool ok = true;
    for (int i = lane; i < 512; i += 32) {
        long long v = p[i];
        if (v < 0 || v >= NN) ok = false;
    }
    unsigned m = __ballot_sync(0xffffffffu, ok);
    if (lane == 0) g_is64 = (m == 0xffffffffu) ? 1 : 0;
}

// ---------------- encoder MLP (x[N,8]->32->64, ELU) + deg init (fused) ----------------
__global__ void encode_kernel(const float* __restrict__ x,
                              const float* __restrict__ W1, const float* __restrict__ b1,
                              const float* __restrict__ W2, const float* __restrict__ b2) {
    __shared__ float sW1[8 * 32], sb1[32], sW2[32 * 64], sb2[64];
    for (int i = threadIdx.x; i < 256; i += blockDim.x) sW1[i] = W1[i];
    for (int i = threadIdx.x; i < 32; i += blockDim.x) sb1[i] = b1[i];
    for (int i = threadIdx.x; i < 2048; i += blockDim.x) sW2[i] = W2[i];
    for (int i = threadIdx.x; i < 64; i += blockDim.x) sb2[i] = b2[i];
    __syncthreads();
    int v = blockIdx.x * blockDim.x + threadIdx.x;
    if (v >= NN) return;
    g_deg[v] = 1;  // self-loop (fused initdeg)
    float xr[8];
#pragma unroll
    for (int k = 0; k < 8; k++) xr[k] = x[v * 8 + k];
    float t[32];
#pragma unroll
    for (int j = 0; j < 32; j++) {
        float s = sb1[j];
#pragma unroll
        for (int k = 0; k < 8; k++) s = fmaf(xr[k], sW1[k * 32 + j], s);
        t[j] = (s > 0.f) ? s : expm1f(s);
    }
    for (int j = 0; j < 64; j++) {
        float s = sb2[j];
#pragma unroll
        for (int k = 0; k < 32; k++) s = fmaf(t[k], sW2[k * 64 + j], s);
        g_hA[v * 64 + j] = (s > 0.f) ? s : expm1f(s);
    }
}

// ---------------- CSR build ----------------
__global__ void hist_kernel(const void* edges) {
    int base = (blockIdx.x * blockDim.x + threadIdx.x) * 4;
    if (base >= EE) return;
    if (g_is64) {
        const long long* p = (const long long*)edges + EE + base;
        longlong4 v = *(const longlong4*)p;
        atomicAdd(&g_deg[(int)v.x], 1);
        atomicAdd(&g_deg[(int)v.y], 1);
        atomicAdd(&g_deg[(int)v.z], 1);
        atomicAdd(&g_deg[(int)v.w], 1);
    } else {
        const int* p = (const int*)edges + EE + base;
        int4 v = *(const int4*)p;
        atomicAdd(&g_deg[v.x], 1);
        atomicAdd(&g_deg[v.y], 1);
        atomicAdd(&g_deg[v.z], 1);
        atomicAdd(&g_deg[v.w], 1);
    }
}

// vectorized: 5x int4 loads, 10x int4 stores per thread
__global__ void scan_kernel() {
    __shared__ int sums[1024];
    int t = threadIdx.x;
    int base = t * 20;
    int local[20];
    int s = 0;
    if (base < NN) {  // NN = 1000*20, so t<1000 fully in range
        const int4* dp = reinterpret_cast<const int4*>(&g_deg[base]);
#pragma unroll
        for (int q = 0; q < 5; q++) {
            int4 v = dp[q];
            local[q * 4 + 0] = s; s += v.x;
            local[q * 4 + 1] = s; s += v.y;
            local[q * 4 + 2] = s; s += v.z;
            local[q * 4 + 3] = s; s += v.w;
        }
    } else {
#pragma unroll
        for (int i = 0; i < 20; i++) local[i] = 0;
    }
    sums[t] = s;
    __syncthreads();
    for (int off = 1; off < 1024; off <<= 1) {
        int v = (t >= off) ? sums[t - off] : 0;
        __syncthreads();
        sums[t] += v;
        __syncthreads();
    }
    int prefix = (t > 0) ? sums[t - 1] : 0;
    if (base < NN) {
        int4* rp = reinterpret_cast<int4*>(&g_rowptr[base]);
        int4* cp = reinterpret_cast<int4*>(&g_cursor[base]);
#pragma unroll
        for (int q = 0; q < 5; q++) {
            int4 v = make_int4(prefix + local[q * 4], prefix + local[q * 4 + 1],
                               prefix + local[q * 4 + 2], prefix + local[q * 4 + 3]);
            rp[q] = v;
            cp[q] = v;
        }
    }
    if (t == 1023) g_rowptr[NN] = sums[1023];
}

__global__ void scatter_kernel(const void* edges) {
    int e = blockIdx.x * blockDim.x + threadIdx.x;
    if (e < EE) {
        int s, d;
        if (g_is64) {
            s = (int)((const long long*)edges)[e];
            d = (int)((const long long*)edges)[EE + e];
        } else {
            s = ((const int*)edges)[e];
            d = ((const int*)edges)[EE + e];
        }
        int pos = atomicAdd(&g_cursor[d], 1);
        g_esrc[pos] = s;
    } else if (e < EE + NN) {
        int v = e - EE;
        int pos = atomicAdd(&g_cursor[v], 1);
        g_esrc[pos] = v;
    }
}

// ---------------- Wad prep: Wad[k][j] = sum_c W[k, h*64+c] * att[h][c] ----------------
__global__ void wadprep_kernel(const float* __restrict__ W,
                               const float* __restrict__ as_, const float* __restrict__ ad_,
                               int l) {
    for (int o = threadIdx.x; o < 512; o += blockDim.x) {
        int k = o >> 3, j = o & 7;
        const float* vec = (j < 4) ? as_ : ad_;
        int h = j & 3;
        const float* wr = W + k * 256 + h * 64;
        const float* vr = vec + h * 64;
        float s = 0.f;
#pragma unroll
        for (int c = 0; c < 64; c++) s = fmaf(wr[c], vr[c], s);
        g_wad[l][k * 8 + j] = s;
    }
}

// ---------------- attention scores from x: a_src/a_dst = x @ Wad (fp32) ----------------
__global__ void att_kernel(int l, int srcA) {
    const float* xin = srcA ? g_hA : g_hB;
    __shared__ float sW[512];
    for (int i = threadIdx.x; i < 512; i += blockDim.x) sW[i] = g_wad[l][i];
    __syncthreads();
    int v = blockIdx.x * blockDim.x + threadIdx.x;
    if (v >= NN) return;
    float acc[8] = {0.f, 0.f, 0.f, 0.f, 0.f, 0.f, 0.f, 0.f};
    const float4* xr = reinterpret_cast<const float4*>(xin + v * 64);
#pragma unroll
    for (int q = 0; q < 16; q++) {
        float4 xv = xr[q];
        const float* w0 = &sW[(q * 4 + 0) * 8];
        const float* w1 = &sW[(q * 4 + 1) * 8];
        const float* w2 = &sW[(q * 4 + 2) * 8];
        const float* w3 = &sW[(q * 4 + 3) * 8];
#pragma unroll
        for (int j = 0; j < 8; j++) {
            acc[j] = fmaf(xv.x, w0[j], acc[j]);
            acc[j] = fmaf(xv.y, w1[j], acc[j]);
            acc[j] = fmaf(xv.z, w2[j], acc[j]);
            acc[j] = fmaf(xv.w, w3[j], acc[j]);
        }
    }
#pragma unroll
    for (int j = 0; j < 4; j++) {
        g_asrc[v * 4 + j] = acc[j];
        g_adst[v * 4 + j] = acc[j + 4];
    }
}

// ---- tensor-core projection GEMM: WMMA fp32 acc, paired-head uint2 epilogue ----
// CTA (bx,by): rows [128bx,128bx+128), heads {2by, 2by+1}. Tiles n and n+4 cover the
// same pair range (8n..8n+7) for the two heads; staging them together lets each
// thread emit 8-byte stores (4 halves = both heads' channel pair), contiguous in the
// interleaved layout at p*8 + 4*by.
#define A_STRIDE 72    // halves per A smem row (64 + 8 pad)
#define B_STRIDE 136   // halves per B smem row (128 + 8 pad)
#define GEMM_SMEM_BYTES (128 * A_STRIDE * 2 + 64 * B_STRIDE * 2)  // 35840

__global__ void __launch_bounds__(256) gemm_kernel(const float* __restrict__ B, int srcA) {
    const float* A = srcA ? g_hA : g_hB;
    __shared__ __align__(16) char smem_raw[GEMM_SMEM_BYTES];
    __half* Ah = reinterpret_cast<__half*>(smem_raw);
    __half* Bh = reinterpret_cast<__half*>(smem_raw + 128 * A_STRIDE * 2);
    int tid = threadIdx.x;
    int lane = tid & 31, w = tid >> 5;
    int rowBase = blockIdx.x * 128;
    int colBase = blockIdx.y * 128;

    // load A tile [128 x 64] fp32 -> fp16
    {
        int r = tid >> 1, cpart = (tid & 1) * 32;
        int gr = rowBase + r;
        if (gr < NN) {
            const float4* src = reinterpret_cast<const float4*>(&A[gr * 64 + cpart]);
#pragma unroll
            for (int j = 0; j < 8; j++) {
                float4 v = src[j];
                *reinterpret_cast<__half2*>(&Ah[r * A_STRIDE + cpart + j * 4]) = __floats2half2_rn(v.x, v.y);
                *reinterpret_cast<__half2*>(&Ah[r * A_STRIDE + cpart + j * 4 + 2]) = __floats2half2_rn(v.z, v.w);
            }
        } else {
            __half2 z = __floats2half2_rn(0.f, 0.f);
#pragma unroll
            for (int j = 0; j < 8; j++) {
                *reinterpret_cast<__half2*>(&Ah[r * A_STRIDE + cpart + j * 4]) = z;
                *reinterpret_cast<__half2*>(&Ah[r * A_STRIDE + cpart + j * 4 + 2]) = z;
            }
        }
    }
    // load B tile [64 x 128] fp32 -> fp16
    {
        int k = tid >> 2, cpart = (tid & 3) * 32;
        const float4* src = reinterpret_cast<const float4*>(&B[k * 256 + colBase + cpart]);
#pragma unroll
        for (int j = 0; j < 8; j++) {
            float4 v = src[j];
            *reinterpret_cast<__half2*>(&Bh[k * B_STRIDE + cpart + j * 4]) = __floats2half2_rn(v.x, v.y);
            *reinterpret_cast<__half2*>(&Bh[k * B_STRIDE + cpart + j * 4 + 2]) = __floats2half2_rn(v.z, v.w);
        }
    }
    __syncthreads();

    wmma::fragment<wmma::accumulator, 16, 16, 16, float> acc[8];
#pragma unroll
    for (int n = 0; n < 8; n++) wmma::fill_fragment(acc[n], 0.f);
#pragma unroll
    for (int k = 0; k < 4; k++) {
        wmma::fragment<wmma::matrix_a, 16, 16, 16, __half, wmma::row_major> af;
        wmma::load_matrix_sync(af, Ah + (w * 16) * A_STRIDE + k * 16, A_STRIDE);
#pragma unroll
        for (int n = 0; n < 8; n++) {
            wmma::fragment<wmma::matrix_b, 16, 16, 16, __half, wmma::row_major> bf;
            wmma::load_matrix_sync(bf, Bh + (k * 16) * B_STRIDE + n * 16, B_STRIDE);
            wmma::mma_sync(acc[n], af, bf, acc[n]);
        }
    }
    __syncthreads();  // mainloop done with Ah/Bh; overlay per-warp staging there

    // epilogue: stage tile pair (n, n+4) = same pairs, heads 2by / 2by+1
    float* st0 = reinterpret_cast<float*>(smem_raw) + w * 512;
    float* st1 = st0 + 256;
    int rr = lane >> 1, cc = (lane & 1) * 8;
    int by4 = blockIdx.y * 4;   // half-offset of this CTA's head pair within the 8-half group
#pragma unroll
    for (int n = 0; n < 4; n++) {
        wmma::store_matrix_sync(st0, acc[n], 16, wmma::mem_row_major);
        wmma::store_matrix_sync(st1, acc[n + 4], 16, wmma::mem_row_major);
        __syncwarp();
        float4 a0 = *reinterpret_cast<const float4*>(st0 + rr * 16 + cc);
        float4 a1 = *reinterpret_cast<const float4*>(st0 + rr * 16 + cc + 4);
        float4 b0 = *reinterpret_cast<const float4*>(st1 + rr * 16 + cc);
        float4 b1 = *reinterpret_cast<const float4*>(st1 + rr * 16 + cc + 4);
        __half* rowp = &g_hproj[(size_t)(rowBase + w * 16 + rr) * 256 + by4];
        int p0 = n * 8 + (cc >> 1);
        __half2 pk[2];
        pk[0] = __floats2half2_rn(a0.x, a0.y); pk[1] = __floats2half2_rn(b0.x, b0.y);
        *reinterpret_cast<uint2*>(rowp + (size_t)(p0 + 0) * 8) = *reinterpret_cast<uint2*>(pk);
        pk[0] = __floats2half2_rn(a0.z, a0.w); pk[1] = __floats2half2_rn(b0.z, b0.w);
        *reinterpret_cast<uint2*>(rowp + (size_t)(p0 + 1) * 8) = *reinterpret_cast<uint2*>(pk);
        pk[0] = __floats2half2_rn(a1.x, a1.y); pk[1] = __floats2half2_rn(b1.x, b1.y);
        *reinterpret_cast<uint2*>(rowp + (size_t)(p0 + 2) * 8) = *reinterpret_cast<uint2*>(pk);
        pk[0] = __floats2half2_rn(a1.z, a1.w); pk[1] = __floats2half2_rn(b1.z, b1.w);
        *reinterpret_cast<uint2*>(rowp + (size_t)(p0 + 3) * 8) = *reinterpret_cast<uint2*>(pk);
        __syncwarp();
    }
}

// ---------------- GAT edge pass: alpha cache + single-LDG.128 interleaved gather ----------------
__device__ __forceinline__ float lrelu(float x) { return fmaxf(x, 0.2f * x); }

__global__ void __launch_bounds__(256) gat_edge_kernel(const float* __restrict__ bias, int srcA) {
    const float* xin = srcA ? g_hA : g_hB;
    float* xout = srcA ? g_hB : g_hA;
    int warp = (blockIdx.x * blockDim.x + threadIdx.x) >> 5;
    int lane = threadIdx.x & 31;
    if (warp >= NN) return;
    int beg = g_rowptr[warp], end = g_rowptr[warp + 1];
    float4 adv = *reinterpret_cast<const float4*>(&g_adst[warp * 4]);

    // pass 1: unnormalized weights w = exp(lrelu(a_src+a_dst)); store + sum.
    float s0 = 0.f, s1 = 0.f, s2 = 0.f, s3 = 0.f;
    for (int e = beg + lane; e < end; e += 32) {
        int s = g_esrc[e];
        float4 av = *reinterpret_cast<const float4*>(&g_asrc[s * 4]);
        float4 wv;
        wv.x = __expf(lrelu(av.x + adv.x));
        wv.y = __expf(lrelu(av.y + adv.y));
        wv.z = __expf(lrelu(av.z + adv.z));
        wv.w = __expf(lrelu(av.w + adv.w));
        *reinterpret_cast<float4*>(&g_alpha[(size_t)e * 4]) = wv;
        s0 += wv.x; s1 += wv.y; s2 += wv.z; s3 += wv.w;
    }
#pragma unroll
    for (int o = 16; o > 0; o >>= 1) {
        s0 += __shfl_xor_sync(0xffffffffu, s0, o);
        s1 += __shfl_xor_sync(0xffffffffu, s1, o);
        s2 += __shfl_xor_sync(0xffffffffu, s2, o);
        s3 += __shfl_xor_sync(0xffffffffu, s3, o);
    }
    float i0 = 1.f / (s0 + 1e-16f);
    float i1 = 1.f / (s1 + 1e-16f);
    float i2 = 1.f / (s2 + 1e-16f);
    float i3 = 1.f / (s3 + 1e-16f);

    // pass 2: one uint4 per edge per lane = lane's channel pair for all 4 heads.
    float accx_a = 0.f, accy_a = 0.f, accx_b = 0.f, accy_b = 0.f;
    for (int base = beg; base < end; base += 32) {
        int cnt = min(32, end - base);
        int s = 0;
        float w0 = 0.f, w1 = 0.f, w2 = 0.f, w3 = 0.f;
        if (lane < cnt) {
            s = g_esrc[base + lane];
            float4 wv = *reinterpret_cast<const float4*>(&g_alpha[(size_t)(base + lane) * 4]);
            w0 = wv.x * i0;
            w1 = wv.y * i1;
            w2 = wv.z * i2;
            w3 = wv.w * i3;
        }
        for (int j = 0; j < cnt; j++) {
            int sj = __shfl_sync(0xffffffffu, s, j);
            float w0j = __shfl_sync(0xffffffffu, w0, j);
            float w1j = __shfl_sync(0xffffffffu, w1, j);
            float w2j = __shfl_sync(0xffffffffu, w2, j);
            float w3j = __shfl_sync(0xffffffffu, w3, j);
            uint4 v = __ldg(reinterpret_cast<const uint4*>(g_hproj + (size_t)sj * 256) + lane);
            const __half2* h2 = reinterpret_cast<const __half2*>(&v);
            float2 f0 = __half22float2(h2[0]);   // head 0, chans 2l,2l+1
            float2 f1 = __half22float2(h2[1]);   // head 1
            float2 f2 = __half22float2(h2[2]);   // head 2
            float2 f3 = __half22float2(h2[3]);   // head 3
            accx_a = fmaf(w0j, f0.x, accx_a);
            accy_a = fmaf(w0j, f0.y, accy_a);
            accx_b = fmaf(w1j, f1.x, accx_b);
            accy_b = fmaf(w1j, f1.y, accy_b);
            accx_a = fmaf(w2j, f2.x, accx_a);
            accy_a = fmaf(w2j, f2.y, accy_a);
            accx_b = fmaf(w3j, f3.x, accx_b);
            accy_b = fmaf(w3j, f3.y, accy_b);
        }
    }
    int c0 = lane * 2;
    float2 bv = *reinterpret_cast<const float2*>(&bias[c0]);
    float2 xv = *reinterpret_cast<const float2*>(&xin[warp * 64 + c0]);
    float2 ov;
    ov.x = (accx_a + accx_b) * 0.25f + bv.x + xv.x;
    ov.y = (accy_a + accy_b) * 0.25f + bv.y + xv.y;
    *reinterpret_cast<float2*>(&xout[warp * 64 + c0]) = ov;
}

// ---------------- output MLP: h3[N,64] -> 64 -> 32 -> 8 ----------------
__global__ void __launch_bounds__(64) outmlp_kernel(
    const float* __restrict__ W1, const float* __restrict__ b1,
    const float* __restrict__ W2, const float* __restrict__ b2,
    const float* __restrict__ W3, const float* __restrict__ b3,
    float* __restrict__ out) {
    __shared__ float sW1[64 * 64], sb1[64], sW2[64 * 32], sb2[32], sW3[32 * 8], sb3[8];
    __shared__ float sh[64 * 65];
    int tid = threadIdx.x;
    for (int i = tid; i < 4096; i += 64) sW1[i] = W1[i];
    if (tid < 64) sb1[tid] = b1[tid];
    for (int i = tid; i < 2048; i += 64) sW2[i] = W2[i];
    if (tid < 32) sb2[tid] = b2[tid];
    for (int i = tid; i < 256; i += 64) sW3[i] = W3[i];
    if (tid < 8) sb3[tid] = b3[tid];
    int vbase = blockIdx.x * 64;
    for (int i = tid; i < 64 * 64; i += 64) {
        int r = i >> 6, c = i & 63;
        int v = vbase + r;
        sh[r * 65 + c] = (v < NN) ? g_hB[v * 64 + c] : 0.f;
    }
    __syncthreads();
    int v = vbase + tid;
    if (v >= NN) return;
    const float* hr = &sh[tid * 65];
    float t1[64];
    for (int j = 0; j < 64; j++) {
        float s = sb1[j];
#pragma unroll
        for (int k = 0; k < 64; k++) s = fmaf(hr[k], sW1[k * 64 + j], s);
        t1[j] = (s > 0.f) ? s : expm1f(s);
    }
    float t2[32];
    for (int j = 0; j < 32; j++) {
        float s = sb2[j];
#pragma unroll
        for (int k = 0; k < 64; k++) s = fmaf(t1[k], sW2[k * 32 + j], s);
        t2[j] = (s > 0.f) ? s : expm1f(s);
    }
    for (int j = 0; j < 8; j++) {
        float s = sb3[j];
#pragma unroll
        for (int k = 0; k < 32; k++) s = fmaf(t2[k], sW3[k * 8 + j], s);
        out[v * 8 + j] = s;
    }
}

// ---------------- launch ----------------
extern "C" void kernel_launch(void* const* d_in, const int* in_sizes, int n_in,
                              void* d_out, int out_size) {
    const float* x = (const float*)d_in[0];
    const void* edges = d_in[1];
    const float* Wenc1 = (const float*)d_in[2];
    const float* benc1 = (const float*)d_in[3];
    const float* Wenc2 = (const float*)d_in[4];
    const float* benc2 = (const float*)d_in[5];
    const float* Wg[3] = {(const float*)d_in[6], (const float*)d_in[10], (const float*)d_in[14]};
    const float* as_[3] = {(const float*)d_in[7], (const float*)d_in[11], (const float*)d_in[15]};
    const float* ad_[3] = {(const float*)d_in[8], (const float*)d_in[12], (const float*)d_in[16]};
    const float* bg[3] = {(const float*)d_in[9], (const float*)d_in[13], (const float*)d_in[17]};
    const float* Wo1 = (const float*)d_in[18];
    const float* bo1 = (const float*)d_in[19];
    const float* Wo2 = (const float*)d_in[20];
    const float* bo2 = (const float*)d_in[21];
    const float* Wo3 = (const float*)d_in[22];
    const float* bo3 = (const float*)d_in[23];
    float* out = (float*)d_out;

    // gemm (layer 1) at launch index 3 for ncu visibility
    detect_kernel<<<1, 32>>>(edges);                                          // 0
    encode_kernel<<<(NN + 255) / 256, 256>>>(x, Wenc1, benc1, Wenc2, benc2);  // 1
    hist_kernel<<<(EE / 4 + 255) / 256, 256>>>(edges);                        // 2
    gemm_kernel<<<dim3(157, 2), 256>>>(Wg[0], 1);                             // 3
    scan_kernel<<<1, 1024>>>();                                               // 4
    scatter_kernel<<<(EE + NN + 255) / 256, 256>>>(edges);                    // 5
    wadprep_kernel<<<1, 256>>>(Wg[0], as_[0], ad_[0], 0);                     // 6
    att_kernel<<<(NN + 255) / 256, 256>>>(0, 1);                              // 7
    gat_edge_kernel<<<2500, 256>>>(bg[0], 1);                                 // 8

    int srcA = 0;
    for (int l = 1; l < 3; l++) {
        wadprep_kernel<<<1, 256>>>(Wg[l], as_[l], ad_[l], l);
        gemm_kernel<<<dim3(157, 2), 256>>>(Wg[l], srcA);
        att_kernel<<<(NN + 255) / 256, 256>>>(l, srcA);
        gat_edge_kernel<<<2500, 256>>>(bg[l], srcA);
        srcA ^= 1;
    }
    // after 3 layers result is in g_hB (A->B->A->B)
    outmlp_kernel<<<(NN + 63) / 64, 64>>>(Wo1, bo1, Wo2, bo2, Wo3, bo3, out);
}